// round 7
// baseline (speedup 1.0000x reference)
#include <cuda_runtime.h>
#include <cuda_bf16.h>
#include <cstdint>
#include <cstddef>

// ---------------- scratch (allocation-free rule: __device__ globals) --------
__device__ float g_Q[512 * 768];
__device__ float g_K[1536 * 768];
__device__ float g_V[1536 * 768];

// ---------------- helpers ---------------------------------------------------
__device__ __forceinline__ void ldmx4(uint32_t* r, uint32_t addr) {
    asm volatile("ldmatrix.sync.aligned.m8n8.x4.shared.b16 {%0,%1,%2,%3}, [%4];"
                 : "=r"(r[0]), "=r"(r[1]), "=r"(r[2]), "=r"(r[3]) : "r"(addr));
}
__device__ __forceinline__ uint32_t smem_u32(const void* p) {
    uint32_t a;
    asm("{ .reg .u64 t; cvta.to.shared.u64 t, %1; cvt.u32.u64 %0, t; }" : "=r"(a) : "l"(p));
    return a;
}
__device__ __forceinline__ void mma_bf16(float* c, const uint32_t* a,
                                         uint32_t b0, uint32_t b1) {
    asm volatile(
        "mma.sync.aligned.m16n8k16.row.col.f32.bf16.bf16.f32 "
        "{%0,%1,%2,%3}, {%4,%5,%6,%7}, {%8,%9}, {%0,%1,%2,%3};"
        : "+f"(c[0]), "+f"(c[1]), "+f"(c[2]), "+f"(c[3])
        : "r"(a[0]), "r"(a[1]), "r"(a[2]), "r"(a[3]), "r"(b0), "r"(b1));
}
__device__ __forceinline__ void split1(float x, unsigned short& h, unsigned short& l) {
    __nv_bfloat16 hb = __float2bfloat16_rn(x);
    float r = x - __bfloat162float(hb);
    __nv_bfloat16 lb = __float2bfloat16_rn(r);
    h = __bfloat16_as_ushort(hb);
    l = __bfloat16_as_ushort(lb);
}

// ---------------- fused QKV GEMM: bf16x3 mma.sync m16n8k16 ------------------
// C = A @ W^T + bias with in-kernel fp32 -> bf16 hi/lo split.
// 224 CTAs of 128 threads, BM=128 x BN=96, K chunked by 16 (48 chunks).
//   [0,32)=Q, [32,128)=K, [128,224)=V.   (2 CTAs fit per SM -> 4 warps/SMSP
//   on doubly-loaded SMs; independent barrier domains overlap bubbles.)
// smem stage (14KB): Ah[4K] Al[4K] Bh[3K] Bl[3K], 32B swizzled rows; x2 bufs.
// 4 warps as 2(m) x 2(n): warp tile 64x48 -> 72 mma per warp per chunk.
#define NCH   48
#define STAGE 14336

__global__ __launch_bounds__(128)
void qkv_gemm_bf16(const float* __restrict__ target, const float* __restrict__ cont,
                   const float* __restrict__ wq, const float* __restrict__ wk,
                   const float* __restrict__ wv,
                   const float* __restrict__ bq, const float* __restrict__ bk,
                   const float* __restrict__ bv) {
    __shared__ __align__(16) char smem[2 * STAGE];

    const int tid = threadIdx.x, lane = tid & 31, wid = tid >> 5;
    const int blk = blockIdx.x;

    int by, bx, plane;
    const float *srcA, *bias;
    float* C;
    if (blk < 32)       { int t = blk;       by = t >> 3; bx = t & 7; srcA = target + (size_t)(by * 128) * 768; plane = 0; bias = bq; C = g_Q; }
    else if (blk < 128) { int t = blk - 32;  by = t >> 3; bx = t & 7; srcA = cont   + (size_t)(by * 128) * 768; plane = 1; bias = bk; C = g_K; }
    else                { int t = blk - 128; by = t >> 3; bx = t & 7; srcA = cont   + (size_t)(by * 128) * 768; plane = 2; bias = bv; C = g_V; }
    const float* srcB = (plane == 0 ? wq : (plane == 1 ? wk : wv)) + (size_t)(bx * 96) * 768;

    // --- load decode: 896 float4 slots per chunk (A 512 + B 384), 7/thread --
    const float* gsrc[7];
    int sdst_hi[7], lo_off[7];
#pragma unroll
    for (int i = 0; i < 7; i++) {
        const int id = i * 128 + tid;
        int row, seg, base;
        if (id < 512) { row = id >> 2;            seg = id & 3; base = 0;    lo_off[i] = 4096;
                        gsrc[i] = srcA + (size_t)row * 768 + seg * 4; }
        else          { const int id2 = id - 512; row = id2 >> 2; seg = id2 & 3; base = 8192; lo_off[i] = 3072;
                        gsrc[i] = srcB + (size_t)row * 768 + seg * 4; }
        const int half = ((seg >> 1) ^ (row >> 2)) & 1;
        sdst_hi[i] = base + row * 32 + half * 16 + (seg & 1) * 8;
    }

    const int warp_m = (wid >> 1) * 64;   // 0 or 64
    const int warp_n = (wid & 1) * 48;    // 0 or 48

    const int a_row = lane & 15;
    const int a_sub = (lane >> 4) & 1;
    const int b_row = ((lane >> 4) & 1) * 8 + (lane & 7);
    const int b_sub = (lane >> 3) & 1;

    const uint32_t sb = smem_u32(smem);

    float acc[4][6][4];
#pragma unroll
    for (int mf = 0; mf < 4; mf++)
#pragma unroll
        for (int j = 0; j < 6; j++)
#pragma unroll
            for (int i = 0; i < 4; i++) acc[mf][j][i] = 0.f;

    float4 r[7];
    // prologue: chunk 0 -> buf 0
#pragma unroll
    for (int i = 0; i < 7; i++) r[i] = *(const float4*)(gsrc[i]);
    {
        char* st = smem;
#pragma unroll
        for (int i = 0; i < 7; i++) {
            unsigned short h0,l0,h1,l1,h2,l2,h3,l3;
            split1(r[i].x, h0, l0); split1(r[i].y, h1, l1);
            split1(r[i].z, h2, l2); split1(r[i].w, h3, l3);
            uint2 ph, pl;
            ph.x = (uint32_t)h0 | ((uint32_t)h1 << 16);
            ph.y = (uint32_t)h2 | ((uint32_t)h3 << 16);
            pl.x = (uint32_t)l0 | ((uint32_t)l1 << 16);
            pl.y = (uint32_t)l2 | ((uint32_t)l3 << 16);
            *(uint2*)(st + sdst_hi[i])             = ph;
            *(uint2*)(st + sdst_hi[i] + lo_off[i]) = pl;
        }
    }
    __syncthreads();
    // preload chunk 1 into registers
#pragma unroll
    for (int i = 0; i < 7; i++) r[i] = *(const float4*)(gsrc[i] + 16);

    for (int c = 0; c < NCH; c++) {
        const int buf = c & 1;
        const uint32_t st = sb + buf * STAGE;

        uint32_t ah[4][4], al[4][4], bh[3][4], bl[3][4];
#pragma unroll
        for (int mf = 0; mf < 4; mf++) {
            const int row = warp_m + mf * 16 + a_row;
            const uint32_t ra = st + row * 32 + ((a_sub ^ (row >> 2)) & 1) * 16;
            ldmx4(ah[mf], ra);
            ldmx4(al[mf], ra + 4096);
        }
#pragma unroll
        for (int ng = 0; ng < 3; ng++) {
            const int row = warp_n + ng * 16 + b_row;
            const uint32_t rb = st + 8192 + row * 32 + ((b_sub ^ (row >> 2)) & 1) * 16;
            ldmx4(bh[ng], rb);
            ldmx4(bl[ng], rb + 3072);
        }

        // store chunk c+1 (held in r) into the other buffer
        if (c + 1 < NCH) {
            char* stn = smem + (buf ^ 1) * STAGE;
#pragma unroll
            for (int i = 0; i < 7; i++) {
                unsigned short h0,l0,h1,l1,h2,l2,h3,l3;
                split1(r[i].x, h0, l0); split1(r[i].y, h1, l1);
                split1(r[i].z, h2, l2); split1(r[i].w, h3, l3);
                uint2 ph, pl;
                ph.x = (uint32_t)h0 | ((uint32_t)h1 << 16);
                ph.y = (uint32_t)h2 | ((uint32_t)h3 << 16);
                pl.x = (uint32_t)l0 | ((uint32_t)l1 << 16);
                pl.y = (uint32_t)l2 | ((uint32_t)l3 << 16);
                *(uint2*)(stn + sdst_hi[i])             = ph;
                *(uint2*)(stn + sdst_hi[i] + lo_off[i]) = pl;
            }
            // LDG for chunk c+2 (clamped); latency hidden under mma below
            const int nc = (c + 2 < NCH) ? (c + 2) : (NCH - 1);
            const size_t off = (size_t)nc * 16;
#pragma unroll
            for (int i = 0; i < 7; i++) r[i] = *(const float4*)(gsrc[i] + off);
        }

        // term-major mma: same-acc RAW deps 24 instructions apart
#pragma unroll
        for (int mf = 0; mf < 4; mf++)
#pragma unroll
            for (int j = 0; j < 6; j++)
                mma_bf16(acc[mf][j], ah[mf], bh[j >> 1][(j & 1) * 2], bh[j >> 1][(j & 1) * 2 + 1]);
#pragma unroll
        for (int mf = 0; mf < 4; mf++)
#pragma unroll
            for (int j = 0; j < 6; j++)
                mma_bf16(acc[mf][j], ah[mf], bl[j >> 1][(j & 1) * 2], bl[j >> 1][(j & 1) * 2 + 1]);
#pragma unroll
        for (int mf = 0; mf < 4; mf++)
#pragma unroll
            for (int j = 0; j < 6; j++)
                mma_bf16(acc[mf][j], al[mf], bh[j >> 1][(j & 1) * 2], bh[j >> 1][(j & 1) * 2 + 1]);

        __syncthreads();
    }

    // epilogue: bias + store fp32
    const int g4 = lane >> 2, t4 = lane & 3;
#pragma unroll
    for (int mf = 0; mf < 4; mf++) {
        const int row = by * 128 + warp_m + mf * 16 + g4;
#pragma unroll
        for (int j = 0; j < 6; j++) {
            const int col = bx * 96 + warp_n + j * 8 + t4 * 2;
            const float2 bb = *(const float2*)&bias[col];
            float2 o0, o1;
            o0.x = acc[mf][j][0] + bb.x; o0.y = acc[mf][j][1] + bb.y;
            o1.x = acc[mf][j][2] + bb.x; o1.y = acc[mf][j][3] + bb.y;
            *(float2*)&C[(size_t)row * 768 + col]       = o0;
            *(float2*)&C[(size_t)(row + 8) * 768 + col] = o1;
        }
    }
}

// ---------------- per-batch epilogue (192 threads, all active) --------------
__global__ __launch_bounds__(192)
void batch_epilogue(const float* __restrict__ p, const float* __restrict__ hmat,
                    const float* __restrict__ g, float* __restrict__ out) {
    const int b = blockIdx.x, tid = threadIdx.x;
    __shared__ float racc[12];
    if (tid < 12) racc[tid] = 0.f;
    __syncthreads();

    const int hh = tid * 4;
    float a[12];
#pragma unroll
    for (int i = 0; i < 12; i++) a[i] = 0.f;

    float4 v4[3];
    const float4 q4 = *(const float4*)&g_Q[(size_t)b * 768 + hh];
#pragma unroll
    for (int mp = 0; mp < 3; mp++) {
        const float4 k4 = *(const float4*)&g_K[((size_t)b * 3 + mp) * 768 + hh];
        v4[mp]          = *(const float4*)&g_V[((size_t)b * 3 + mp) * 768 + hh];
        const float4 pm = *(const float4*)&p[mp * 768 + hh];
        a[mp] += pm.x * q4.x + pm.y * q4.y + pm.z * q4.z + pm.w * q4.w;

        const float4* hrp = (const float4*)&hmat[((size_t)(mp * 768 + hh)) * 3];
        const float4 f0 = hrp[0], f1 = hrp[1], f2 = hrp[2];
        const float hr[12] = {f0.x, f0.y, f0.z, f0.w, f1.x, f1.y,
                              f1.z, f1.w, f2.x, f2.y, f2.z, f2.w};
        const float t[4] = {q4.x * k4.x, q4.y * k4.y, q4.z * k4.z, q4.w * k4.w};
#pragma unroll
        for (int e = 0; e < 4; e++) {
            a[3] += t[e] * hr[e * 3 + 0];
            a[4] += t[e] * hr[e * 3 + 1];
            a[5] += t[e] * hr[e * 3 + 2];
        }
    }
    const float4 v0 = v4[0], v1 = v4[1], v2 = v4[2];
    a[6]  += v0.x*v0.x + v0.y*v0.y + v0.z*v0.z + v0.w*v0.w;
    a[7]  += v0.x*v1.x + v0.y*v1.y + v0.z*v1.z + v0.w*v1.w;
    a[8]  += v0.x*v2.x + v0.y*v2.y + v0.z*v2.z + v0.w*v2.w;
    a[9]  += v1.x*v1.x + v1.y*v1.y + v1.z*v1.z + v1.w*v1.w;
    a[10] += v1.x*v2.x + v1.y*v2.y + v1.z*v2.z + v1.w*v2.w;
    a[11] += v2.x*v2.x + v2.y*v2.y + v2.z*v2.z + v2.w*v2.w;

#pragma unroll
    for (int i = 0; i < 12; i++) {
        float v = a[i];
#pragma unroll
        for (int off = 16; off; off >>= 1)
            v += __shfl_down_sync(0xffffffffu, v, off);
        if ((tid & 31) == 0) atomicAdd(&racc[i], v);
    }
    __syncthreads();

    const float ker0 = racc[0] + racc[3];
    const float ker1 = racc[1] + racc[4];
    const float ker2 = racc[2] + racc[5];
    const float c0 = ker0 * racc[6] + ker1 * racc[7]  + ker2 * racc[8];
    const float c1 = ker0 * racc[7] + ker1 * racc[9]  + ker2 * racc[10];
    const float c2 = ker0 * racc[8] + ker1 * racc[10] + ker2 * racc[11];
    const float4 g0 = *(const float4*)&g[hh];
    const float4 g1 = *(const float4*)&g[768 + hh];
    const float4 g2 = *(const float4*)&g[1536 + hh];
    float4 o;
    o.x = ker0*v4[0].x + ker1*v4[1].x + ker2*v4[2].x + c0*g0.x + c1*g1.x + c2*g2.x;
    o.y = ker0*v4[0].y + ker1*v4[1].y + ker2*v4[2].y + c0*g0.y + c1*g1.y + c2*g2.y;
    o.z = ker0*v4[0].z + ker1*v4[1].z + ker2*v4[2].z + c0*g0.z + c1*g1.z + c2*g2.z;
    o.w = ker0*v4[0].w + ker1*v4[1].w + ker2*v4[2].w + c0*g0.w + c1*g1.w + c2*g2.w;
    *(float4*)&out[(size_t)b * 768 + hh] = o;
}

// ---------------- launch -----------------------------------------------------
extern "C" void kernel_launch(void* const* d_in, const int* in_sizes, int n_in,
                              void* d_out, int out_size) {
    const float* target = (const float*)d_in[0];
    const float* cont   = (const float*)d_in[1];
    const float* Wq     = (const float*)d_in[2];
    const float* bq     = (const float*)d_in[3];
    const float* Wk     = (const float*)d_in[4];
    const float* bk     = (const float*)d_in[5];
    const float* Wv     = (const float*)d_in[6];
    const float* bv     = (const float*)d_in[7];
    const float* p      = (const float*)d_in[8];
    const float* hmat   = (const float*)d_in[9];
    const float* g      = (const float*)d_in[10];
    float* out = (float*)d_out;

    qkv_gemm_bf16<<<224, 128>>>(target, cont, Wq, Wk, Wv, bq, bk, bv);
    batch_epilogue<<<512, 192>>>(p, hmat, g, out);
}

// round 9
// speedup vs baseline: 1.3038x; 1.3038x over previous
#include <cuda_runtime.h>
#include <cuda_bf16.h>
#include <cstdint>
#include <cstddef>

// ---------------- scratch (allocation-free rule: __device__ globals) --------
__device__ float g_Q[512 * 768];
__device__ float g_K[1536 * 768];
__device__ float g_V[1536 * 768];
// W bf16 hi/lo planes: [3][768][768] each (Wq|Wk|Wv)
__device__ __align__(16) __nv_bfloat16 g_Wbh[3 * 768 * 768];
__device__ __align__(16) __nv_bfloat16 g_Wbl[3 * 768 * 768];

// ---------------- helpers ---------------------------------------------------
__device__ __forceinline__ void ldmx4(uint32_t* r, uint32_t addr) {
    asm volatile("ldmatrix.sync.aligned.m8n8.x4.shared.b16 {%0,%1,%2,%3}, [%4];"
                 : "=r"(r[0]), "=r"(r[1]), "=r"(r[2]), "=r"(r[3]) : "r"(addr));
}
__device__ __forceinline__ uint32_t smem_u32(const void* p) {
    uint32_t a;
    asm("{ .reg .u64 t; cvta.to.shared.u64 t, %1; cvt.u32.u64 %0, t; }" : "=r"(a) : "l"(p));
    return a;
}
__device__ __forceinline__ void cp16(uint32_t dst, const void* src) {
    asm volatile("cp.async.cg.shared.global [%0], [%1], 16;" :: "r"(dst), "l"(src) : "memory");
}
__device__ __forceinline__ void mma_bf16(float* c, const uint32_t* a,
                                         uint32_t b0, uint32_t b1) {
    asm volatile(
        "mma.sync.aligned.m16n8k16.row.col.f32.bf16.bf16.f32 "
        "{%0,%1,%2,%3}, {%4,%5,%6,%7}, {%8,%9}, {%0,%1,%2,%3};"
        : "+f"(c[0]), "+f"(c[1]), "+f"(c[2]), "+f"(c[3])
        : "r"(a[0]), "r"(a[1]), "r"(a[2]), "r"(a[3]), "r"(b0), "r"(b1));
}
__device__ __forceinline__ void split1(float x, unsigned short& h, unsigned short& l) {
    __nv_bfloat16 hb = __float2bfloat16_rn(x);
    float r = x - __bfloat162float(hb);
    __nv_bfloat16 lb = __float2bfloat16_rn(r);
    h = __bfloat16_as_ushort(hb);
    l = __bfloat16_as_ushort(lb);
}
__device__ __forceinline__ void split4_store(char* base_hi, int off, int lo_off, float4 x) {
    unsigned short h0,l0,h1,l1,h2,l2,h3,l3;
    split1(x.x, h0, l0); split1(x.y, h1, l1);
    split1(x.z, h2, l2); split1(x.w, h3, l3);
    uint2 ph, pl;
    ph.x = (uint32_t)h0 | ((uint32_t)h1 << 16);
    ph.y = (uint32_t)h2 | ((uint32_t)h3 << 16);
    pl.x = (uint32_t)l0 | ((uint32_t)l1 << 16);
    pl.y = (uint32_t)l2 | ((uint32_t)l3 << 16);
    *(uint2*)(base_hi + off)          = ph;
    *(uint2*)(base_hi + off + lo_off) = pl;
}

// ---------------- W prepass: fp32 -> bf16 hi/lo planes ----------------------
// 442368 float4 slots (147456 per W matrix).
__global__ __launch_bounds__(256)
void split_w_kernel(const float* __restrict__ wq, const float* __restrict__ wk,
                    const float* __restrict__ wv) {
    const int idx = blockIdx.x * 256 + threadIdx.x;
    if (idx >= 442368) return;
    const int plane = idx / 147456, wi = idx - plane * 147456;
    const float4* s = (const float4*)(plane == 0 ? wq : (plane == 1 ? wk : wv));
    const float4 x = s[wi];
    unsigned short h0,l0,h1,l1,h2,l2,h3,l3;
    split1(x.x, h0, l0); split1(x.y, h1, l1);
    split1(x.z, h2, l2); split1(x.w, h3, l3);
    uint2 ph, pl;
    ph.x = (uint32_t)h0 | ((uint32_t)h1 << 16);
    ph.y = (uint32_t)h2 | ((uint32_t)h3 << 16);
    pl.x = (uint32_t)l0 | ((uint32_t)l1 << 16);
    pl.y = (uint32_t)l2 | ((uint32_t)l3 << 16);
    ((uint2*)g_Wbh)[idx] = ph;
    ((uint2*)g_Wbl)[idx] = pl;
}

// ---------------- fused QKV GEMM: bf16x3 mma.sync m16n8k16 ------------------
// C = A @ W^T + bias. A split fp32->bf16 hi/lo in-kernel (register-staged);
// W loaded as prepass bf16 planes via cp.async (no cvt in mainloop).
// 112 CTAs (single wave), 256 thr, BM=128 x BN=192, K chunked 16 (48 chunks).
//   [0,16)=Q, [16,64)=K, [64,112)=V.
// smem stage 20KB: Ah[0,4K) Al[4K,8K) Bh[8K,14K) Bl[14K,20K), 32B swizzled
// rows; double buffered. 8 warps as 2(m) x 4(n): warp tile 64x48 -> 72 mma.
#define NCH   48
#define STAGE 20480

__global__ __launch_bounds__(256)
void qkv_gemm_bf16(const float* __restrict__ target, const float* __restrict__ cont,
                   const float* __restrict__ bq, const float* __restrict__ bk,
                   const float* __restrict__ bv) {
    __shared__ __align__(16) char smem[2 * STAGE];
    const uint32_t sb = smem_u32(smem);

    const int tid = threadIdx.x, lane = tid & 31, wid = tid >> 5;
    const int blk = blockIdx.x;

    int by, bx, plane;
    const float *srcA, *bias;
    float* C;
    if (blk < 16)      { int t = blk;      by = t >> 2; bx = t & 3; srcA = target + (size_t)(by * 128) * 768; plane = 0; bias = bq; C = g_Q; }
    else if (blk < 64) { int t = blk - 16; by = t >> 2; bx = t & 3; srcA = cont   + (size_t)(by * 128) * 768; plane = 1; bias = bk; C = g_K; }
    else               { int t = blk - 64; by = t >> 2; bx = t & 3; srcA = cont   + (size_t)(by * 128) * 768; plane = 2; bias = bv; C = g_V; }

    const char* Wh = (const char*)g_Wbh + (size_t)plane * 1179648 + (size_t)(bx * 192) * 1536;
    const char* Wl = (const char*)g_Wbl + (size_t)plane * 1179648 + (size_t)(bx * 192) * 1536;

    // --- A decode: 512 fp32-float4 slots per chunk, 2 per thread -------------
    const float* gA[2];
    int dA[2];
#pragma unroll
    for (int i = 0; i < 2; i++) {
        const int id = i * 256 + tid;
        const int row = id >> 2, seg = id & 3;
        gA[i] = srcA + (size_t)row * 768 + seg * 4;
        dA[i] = row * 32 + (((seg >> 1) ^ (row >> 2)) & 1) * 16 + (seg & 1) * 8;
    }
    // --- B decode: 768 bf16-16B slots per chunk, 3 per thread (cp.async) ----
    const char* gB[3];
    uint32_t dB[3];                      // stage-relative smem offsets
#pragma unroll
    for (int i = 0; i < 3; i++) {
        const int id = i * 256 + tid;                 // 0..767
        const int pl = (id >= 384) ? 1 : 0;
        const int rem = id - pl * 384, row = rem >> 1, sub = rem & 1;
        gB[i] = (pl ? Wl : Wh) + (size_t)row * 1536 + sub * 16;
        dB[i] = 8192 + pl * 6144 + row * 32 + ((sub ^ (row >> 2)) & 1) * 16;
    }

    const int warp_m = (wid >> 2) * 64;
    const int warp_n = (wid & 3) * 48;

    const int a_row = lane & 15;
    const int a_sub = (lane >> 4) & 1;
    const int b_row = ((lane >> 4) & 1) * 8 + (lane & 7);
    const int b_sub = (lane >> 3) & 1;

    float acc[4][6][4];
#pragma unroll
    for (int mf = 0; mf < 4; mf++)
#pragma unroll
        for (int j = 0; j < 6; j++)
#pragma unroll
            for (int i = 0; i < 4; i++) acc[mf][j][i] = 0.f;

    float4 rA[2];
    // prologue: chunk 0 -> buf 0
#pragma unroll
    for (int i = 0; i < 2; i++) rA[i] = *(const float4*)(gA[i]);
#pragma unroll
    for (int i = 0; i < 2; i++) split4_store(smem, dA[i], 4096, rA[i]);
#pragma unroll
    for (int i = 0; i < 3; i++) cp16(sb + dB[i], gB[i]);
    asm volatile("cp.async.commit_group;" ::: "memory");
    asm volatile("cp.async.wait_group 0;" ::: "memory");
    __syncthreads();
    // preload A chunk 1
#pragma unroll
    for (int i = 0; i < 2; i++) rA[i] = *(const float4*)(gA[i] + 16);

    for (int c = 0; c < NCH; c++) {
        const int buf = c & 1;
        const uint32_t st = sb + buf * STAGE;
        const uint32_t stn_off = (uint32_t)((buf ^ 1) * STAGE);

        uint32_t ah[4][4], al[4][4], bh[3][4], bl[3][4];
#pragma unroll
        for (int mf = 0; mf < 4; mf++) {
            const int row = warp_m + mf * 16 + a_row;
            const uint32_t ra = st + row * 32 + ((a_sub ^ (row >> 2)) & 1) * 16;
            ldmx4(ah[mf], ra);
            ldmx4(al[mf], ra + 4096);
        }
#pragma unroll
        for (int ng = 0; ng < 3; ng++) {
            const int row = warp_n + ng * 16 + b_row;
            const uint32_t rb = st + 8192 + row * 32 + ((b_sub ^ (row >> 2)) & 1) * 16;
            ldmx4(bh[ng], rb);
            ldmx4(bl[ng], rb + 6144);
        }

        const bool more = (c + 1 < NCH);
        if (more) {
            // A: store chunk c+1 (in regs) into other buffer, then LDG c+2
            char* stn = smem + stn_off;
#pragma unroll
            for (int i = 0; i < 2; i++) split4_store(stn, dA[i], 4096, rA[i]);
            // B: cp.async chunk c+1 into other buffer (FIX: include sb base)
            const size_t boff = (size_t)(c + 1) * 32;
#pragma unroll
            for (int i = 0; i < 3; i++) cp16(sb + stn_off + dB[i], gB[i] + boff);
            asm volatile("cp.async.commit_group;" ::: "memory");
            const int nc = (c + 2 < NCH) ? (c + 2) : (NCH - 1);
            const size_t aoff = (size_t)nc * 16;
#pragma unroll
            for (int i = 0; i < 2; i++) rA[i] = *(const float4*)(gA[i] + aoff);
        }

        // term-major mma: same-acc RAW deps 24 instructions apart
#pragma unroll
        for (int mf = 0; mf < 4; mf++)
#pragma unroll
            for (int j = 0; j < 6; j++)
                mma_bf16(acc[mf][j], ah[mf], bh[j >> 1][(j & 1) * 2], bh[j >> 1][(j & 1) * 2 + 1]);
#pragma unroll
        for (int mf = 0; mf < 4; mf++)
#pragma unroll
            for (int j = 0; j < 6; j++)
                mma_bf16(acc[mf][j], ah[mf], bl[j >> 1][(j & 1) * 2], bl[j >> 1][(j & 1) * 2 + 1]);
#pragma unroll
        for (int mf = 0; mf < 4; mf++)
#pragma unroll
            for (int j = 0; j < 6; j++)
                mma_bf16(acc[mf][j], al[mf], bh[j >> 1][(j & 1) * 2], bh[j >> 1][(j & 1) * 2 + 1]);

        if (more) asm volatile("cp.async.wait_group 0;" ::: "memory");
        __syncthreads();
    }

    // epilogue: bias + store fp32
    const int g4 = lane >> 2, t4 = lane & 3;
#pragma unroll
    for (int mf = 0; mf < 4; mf++) {
        const int row = by * 128 + warp_m + mf * 16 + g4;
#pragma unroll
        for (int j = 0; j < 6; j++) {
            const int col = bx * 192 + warp_n + j * 8 + t4 * 2;
            const float2 bb = *(const float2*)&bias[col];
            float2 o0, o1;
            o0.x = acc[mf][j][0] + bb.x; o0.y = acc[mf][j][1] + bb.y;
            o1.x = acc[mf][j][2] + bb.x; o1.y = acc[mf][j][3] + bb.y;
            *(float2*)&C[(size_t)row * 768 + col]       = o0;
            *(float2*)&C[(size_t)(row + 8) * 768 + col] = o1;
        }
    }
}

// ---------------- per-batch epilogue (no atomics) ---------------------------
__global__ __launch_bounds__(192)
void batch_epilogue(const float* __restrict__ p, const float* __restrict__ hmat,
                    const float* __restrict__ g, float* __restrict__ out) {
    const int b = blockIdx.x, tid = threadIdx.x;
    const int lane = tid & 31, wid = tid >> 5;
    __shared__ float wacc[6][12];
    __shared__ float racc[12];

    const int hh = tid * 4;
    float a[12];
#pragma unroll
    for (int i = 0; i < 12; i++) a[i] = 0.f;

    float4 v4[3];
    const float4 q4 = *(const float4*)&g_Q[(size_t)b * 768 + hh];
#pragma unroll
    for (int mp = 0; mp < 3; mp++) {
        const float4 k4 = *(const float4*)&g_K[((size_t)b * 3 + mp) * 768 + hh];
        v4[mp]          = *(const float4*)&g_V[((size_t)b * 3 + mp) * 768 + hh];
        const float4 pm = *(const float4*)&p[mp * 768 + hh];
        a[mp] += pm.x * q4.x + pm.y * q4.y + pm.z * q4.z + pm.w * q4.w;

        const float4* hrp = (const float4*)&hmat[((size_t)(mp * 768 + hh)) * 3];
        const float4 f0 = hrp[0], f1 = hrp[1], f2 = hrp[2];
        const float hr[12] = {f0.x, f0.y, f0.z, f0.w, f1.x, f1.y,
                              f1.z, f1.w, f2.x, f2.y, f2.z, f2.w};
        const float t[4] = {q4.x * k4.x, q4.y * k4.y, q4.z * k4.z, q4.w * k4.w};
#pragma unroll
        for (int e = 0; e < 4; e++) {
            a[3] += t[e] * hr[e * 3 + 0];
            a[4] += t[e] * hr[e * 3 + 1];
            a[5] += t[e] * hr[e * 3 + 2];
        }
    }
    const float4 v0 = v4[0], v1 = v4[1], v2 = v4[2];
    a[6]  += v0.x*v0.x + v0.y*v0.y + v0.z*v0.z + v0.w*v0.w;
    a[7]  += v0.x*v1.x + v0.y*v1.y + v0.z*v1.z + v0.w*v1.w;
    a[8]  += v0.x*v2.x + v0.y*v2.y + v0.z*v2.z + v0.w*v2.w;
    a[9]  += v1.x*v1.x + v1.y*v1.y + v1.z*v1.z + v1.w*v1.w;
    a[10] += v1.x*v2.x + v1.y*v2.y + v1.z*v2.z + v1.w*v2.w;
    a[11] += v2.x*v2.x + v2.y*v2.y + v2.z*v2.z + v2.w*v2.w;

#pragma unroll
    for (int i = 0; i < 12; i++) {
        float v = a[i];
#pragma unroll
        for (int off = 16; off; off >>= 1)
            v += __shfl_down_sync(0xffffffffu, v, off);
        if (lane == 0) wacc[wid][i] = v;
    }
    __syncthreads();
    if (tid < 12) {
        float s = 0.f;
#pragma unroll
        for (int w = 0; w < 6; w++) s += wacc[w][tid];
        racc[tid] = s;
    }
    __syncthreads();

    const float ker0 = racc[0] + racc[3];
    const float ker1 = racc[1] + racc[4];
    const float ker2 = racc[2] + racc[5];
    const float c0 = ker0 * racc[6] + ker1 * racc[7]  + ker2 * racc[8];
    const float c1 = ker0 * racc[7] + ker1 * racc[9]  + ker2 * racc[10];
    const float c2 = ker0 * racc[8] + ker1 * racc[10] + ker2 * racc[11];
    const float4 g0 = *(const float4*)&g[hh];
    const float4 g1 = *(const float4*)&g[768 + hh];
    const float4 g2 = *(const float4*)&g[1536 + hh];
    float4 o;
    o.x = ker0*v4[0].x + ker1*v4[1].x + ker2*v4[2].x + c0*g0.x + c1*g1.x + c2*g2.x;
    o.y = ker0*v4[0].y + ker1*v4[1].y + ker2*v4[2].y + c0*g0.y + c1*g1.y + c2*g2.y;
    o.z = ker0*v4[0].z + ker1*v4[1].z + ker2*v4[2].z + c0*g0.z + c1*g1.z + c2*g2.z;
    o.w = ker0*v4[0].w + ker1*v4[1].w + ker2*v4[2].w + c0*g0.w + c1*g1.w + c2*g2.w;
    *(float4*)&out[(size_t)b * 768 + hh] = o;
}

// ---------------- launch -----------------------------------------------------
extern "C" void kernel_launch(void* const* d_in, const int* in_sizes, int n_in,
                              void* d_out, int out_size) {
    const float* target = (const float*)d_in[0];
    const float* cont   = (const float*)d_in[1];
    const float* Wq     = (const float*)d_in[2];
    const float* bq     = (const float*)d_in[3];
    const float* Wk     = (const float*)d_in[4];
    const float* bk     = (const float*)d_in[5];
    const float* Wv     = (const float*)d_in[6];
    const float* bv     = (const float*)d_in[7];
    const float* p      = (const float*)d_in[8];
    const float* hmat   = (const float*)d_in[9];
    const float* g      = (const float*)d_in[10];
    float* out = (float*)d_out;

    split_w_kernel<<<1728, 256>>>(Wq, Wk, Wv);
    qkv_gemm_bf16<<<112, 256>>>(target, cont, bq, bk, bv);
    batch_epilogue<<<512, 192>>>(p, hmat, g, out);
}

// round 10
// speedup vs baseline: 2.1056x; 1.6150x over previous
#include <cuda_runtime.h>
#include <cuda_fp16.h>
#include <cstdint>
#include <cstddef>

// ---------------- scratch (allocation-free rule: __device__ globals) --------
__device__ float g_Q[512 * 768];
__device__ float g_K[1536 * 768];
__device__ float g_V[1536 * 768];

// ---------------- helpers ---------------------------------------------------
__device__ __forceinline__ void ldmx4(uint32_t* r, uint32_t addr) {
    asm volatile("ldmatrix.sync.aligned.m8n8.x4.shared.b16 {%0,%1,%2,%3}, [%4];"
                 : "=r"(r[0]), "=r"(r[1]), "=r"(r[2]), "=r"(r[3]) : "r"(addr));
}
__device__ __forceinline__ uint32_t smem_u32(const void* p) {
    uint32_t a;
    asm("{ .reg .u64 t; cvta.to.shared.u64 t, %1; cvt.u32.u64 %0, t; }" : "=r"(a) : "l"(p));
    return a;
}
__device__ __forceinline__ void mma_f16(float* c, const uint32_t* a,
                                        uint32_t b0, uint32_t b1) {
    asm volatile(
        "mma.sync.aligned.m16n8k16.row.col.f32.f16.f16.f32 "
        "{%0,%1,%2,%3}, {%4,%5,%6,%7}, {%8,%9}, {%0,%1,%2,%3};"
        : "+f"(c[0]), "+f"(c[1]), "+f"(c[2]), "+f"(c[3])
        : "r"(a[0]), "r"(a[1]), "r"(a[2]), "r"(a[3]), "r"(b0), "r"(b1));
}
// fp16 hi/lo split: x = h + l to ~22 mantissa bits
__device__ __forceinline__ void split1h(float x, unsigned short& h, unsigned short& l) {
    __half hb = __float2half_rn(x);
    float r = x - __half2float(hb);
    __half lb = __float2half_rn(r);
    h = __half_as_ushort(hb);
    l = __half_as_ushort(lb);
}
__device__ __forceinline__ void split4h_store(char* base_hi, int off, int lo_off, float4 x) {
    unsigned short h0,l0,h1,l1,h2,l2,h3,l3;
    split1h(x.x, h0, l0); split1h(x.y, h1, l1);
    split1h(x.z, h2, l2); split1h(x.w, h3, l3);
    uint2 ph, pl;
    ph.x = (uint32_t)h0 | ((uint32_t)h1 << 16);
    ph.y = (uint32_t)h2 | ((uint32_t)h3 << 16);
    pl.x = (uint32_t)l0 | ((uint32_t)l1 << 16);
    pl.y = (uint32_t)l2 | ((uint32_t)l3 << 16);
    *(uint2*)(base_hi + off)          = ph;
    *(uint2*)(base_hi + off + lo_off) = pl;
}
__device__ __forceinline__ void cvt4h_store(char* base, int off, float4 x) {
    uint2 ph;
    ph.x = (uint32_t)__half_as_ushort(__float2half_rn(x.x)) |
           ((uint32_t)__half_as_ushort(__float2half_rn(x.y)) << 16);
    ph.y = (uint32_t)__half_as_ushort(__float2half_rn(x.z)) |
           ((uint32_t)__half_as_ushort(__float2half_rn(x.w)) << 16);
    *(uint2*)(base + off) = ph;
}

// ---------------- fused QKV GEMM: fp16x2 mma.sync m16n8k16 ------------------
// C = A @ W^T + bias. A split fp32 -> fp16 hi/lo (exact to ~22 bits), W in
// plain fp16 (err ~2^-12): D = Ah*B + Al*B  (2 mma terms, was 3).
// 112 CTAs (single wave), 256 thr, BM=128 x BN=192, K chunked 16 (48 chunks).
//   [0,16)=Q, [16,64)=K, [64,112)=V.
// smem stage 14KB: Ah[0,4K) Al[4K,8K) B[8K,14K), 32B swizzled rows; x2 bufs.
// 8 warps as 2(m) x 4(n): warp tile 64x48 -> 48 mma per warp per chunk.
#define NCH   48
#define STAGE 14336

__global__ __launch_bounds__(256)
void qkv_gemm_f16(const float* __restrict__ target, const float* __restrict__ cont,
                  const float* __restrict__ wq, const float* __restrict__ wk,
                  const float* __restrict__ wv,
                  const float* __restrict__ bq, const float* __restrict__ bk,
                  const float* __restrict__ bv) {
    __shared__ __align__(16) char smem[2 * STAGE];
    const uint32_t sb = smem_u32(smem);

    const int tid = threadIdx.x, lane = tid & 31, wid = tid >> 5;
    const int blk = blockIdx.x;

    int by, bx, plane;
    const float *srcA, *bias;
    float* C;
    if (blk < 16)      { int t = blk;      by = t >> 2; bx = t & 3; srcA = target + (size_t)(by * 128) * 768; plane = 0; bias = bq; C = g_Q; }
    else if (blk < 64) { int t = blk - 16; by = t >> 2; bx = t & 3; srcA = cont   + (size_t)(by * 128) * 768; plane = 1; bias = bk; C = g_K; }
    else               { int t = blk - 64; by = t >> 2; bx = t & 3; srcA = cont   + (size_t)(by * 128) * 768; plane = 2; bias = bv; C = g_V; }
    const float* srcB = (plane == 0 ? wq : (plane == 1 ? wk : wv)) + (size_t)(bx * 192) * 768;

    // --- A decode: 512 fp32-float4 slots per chunk, 2 per thread -------------
    const float* gA[2];
    int dA[2];
#pragma unroll
    for (int i = 0; i < 2; i++) {
        const int id = i * 256 + tid;
        const int row = id >> 2, seg = id & 3;
        gA[i] = srcA + (size_t)row * 768 + seg * 4;
        dA[i] = row * 32 + (((seg >> 1) ^ (row >> 2)) & 1) * 16 + (seg & 1) * 8;
    }
    // --- B decode: 768 fp32-float4 slots per chunk, 3 per thread -------------
    const float* gB[3];
    int dB[3];
#pragma unroll
    for (int i = 0; i < 3; i++) {
        const int id = i * 256 + tid;               // 0..767
        const int row = id >> 2, seg = id & 3;      // row 0..191
        gB[i] = srcB + (size_t)row * 768 + seg * 4;
        dB[i] = 8192 + row * 32 + (((seg >> 1) ^ (row >> 2)) & 1) * 16 + (seg & 1) * 8;
    }

    const int warp_m = (wid >> 2) * 64;
    const int warp_n = (wid & 3) * 48;

    const int a_row = lane & 15;
    const int a_sub = (lane >> 4) & 1;
    const int b_row = ((lane >> 4) & 1) * 8 + (lane & 7);
    const int b_sub = (lane >> 3) & 1;

    float acc[4][6][4];
#pragma unroll
    for (int mf = 0; mf < 4; mf++)
#pragma unroll
        for (int j = 0; j < 6; j++)
#pragma unroll
            for (int i = 0; i < 4; i++) acc[mf][j][i] = 0.f;

    float4 rA[2], rB[3];
    // prologue: chunk 0 -> buf 0
#pragma unroll
    for (int i = 0; i < 2; i++) rA[i] = *(const float4*)(gA[i]);
#pragma unroll
    for (int i = 0; i < 3; i++) rB[i] = *(const float4*)(gB[i]);
#pragma unroll
    for (int i = 0; i < 2; i++) split4h_store(smem, dA[i], 4096, rA[i]);
#pragma unroll
    for (int i = 0; i < 3; i++) cvt4h_store(smem, dB[i], rB[i]);
    __syncthreads();
    // preload chunk 1
#pragma unroll
    for (int i = 0; i < 2; i++) rA[i] = *(const float4*)(gA[i] + 16);
#pragma unroll
    for (int i = 0; i < 3; i++) rB[i] = *(const float4*)(gB[i] + 16);

    for (int c = 0; c < NCH; c++) {
        const int buf = c & 1;
        const uint32_t st = sb + buf * STAGE;

        uint32_t ah[4][4], al[4][4], bf[3][4];
#pragma unroll
        for (int mf = 0; mf < 4; mf++) {
            const int row = warp_m + mf * 16 + a_row;
            const uint32_t ra = st + row * 32 + ((a_sub ^ (row >> 2)) & 1) * 16;
            ldmx4(ah[mf], ra);
            ldmx4(al[mf], ra + 4096);
        }
#pragma unroll
        for (int ng = 0; ng < 3; ng++) {
            const int row = warp_n + ng * 16 + b_row;
            const uint32_t rb = st + 8192 + row * 32 + ((b_sub ^ (row >> 2)) & 1) * 16;
            ldmx4(bf[ng], rb);
        }

        const bool more = (c + 1 < NCH);
        if (more) {
            // store chunk c+1 (in regs) into the other buffer
            char* stn = smem + (buf ^ 1) * STAGE;
#pragma unroll
            for (int i = 0; i < 2; i++) split4h_store(stn, dA[i], 4096, rA[i]);
#pragma unroll
            for (int i = 0; i < 3; i++) cvt4h_store(stn, dB[i], rB[i]);
            // LDG chunk c+2 (clamped); latency hidden under mma below
            const int nc = (c + 2 < NCH) ? (c + 2) : (NCH - 1);
            const size_t off = (size_t)nc * 16;
#pragma unroll
            for (int i = 0; i < 2; i++) rA[i] = *(const float4*)(gA[i] + off);
#pragma unroll
            for (int i = 0; i < 3; i++) rB[i] = *(const float4*)(gB[i] + off);
        }

        // term-major mma: same-acc RAW deps 24 instructions apart
#pragma unroll
        for (int mf = 0; mf < 4; mf++)
#pragma unroll
            for (int j = 0; j < 6; j++)
                mma_f16(acc[mf][j], ah[mf], bf[j >> 1][(j & 1) * 2], bf[j >> 1][(j & 1) * 2 + 1]);
#pragma unroll
        for (int mf = 0; mf < 4; mf++)
#pragma unroll
            for (int j = 0; j < 6; j++)
                mma_f16(acc[mf][j], al[mf], bf[j >> 1][(j & 1) * 2], bf[j >> 1][(j & 1) * 2 + 1]);

        __syncthreads();
    }

    // epilogue: bias + store fp32
    const int g4 = lane >> 2, t4 = lane & 3;
#pragma unroll
    for (int mf = 0; mf < 4; mf++) {
        const int row = by * 128 + warp_m + mf * 16 + g4;
#pragma unroll
        for (int j = 0; j < 6; j++) {
            const int col = bx * 192 + warp_n + j * 8 + t4 * 2;
            const float2 bb = *(const float2*)&bias[col];
            float2 o0, o1;
            o0.x = acc[mf][j][0] + bb.x; o0.y = acc[mf][j][1] + bb.y;
            o1.x = acc[mf][j][2] + bb.x; o1.y = acc[mf][j][3] + bb.y;
            *(float2*)&C[(size_t)row * 768 + col]       = o0;
            *(float2*)&C[(size_t)(row + 8) * 768 + col] = o1;
        }
    }
}

// ---------------- per-batch epilogue (atomic-free tree reduce) --------------
__global__ __launch_bounds__(192)
void batch_epilogue(const float* __restrict__ p, const float* __restrict__ hmat,
                    const float* __restrict__ g, float* __restrict__ out) {
    const int b = blockIdx.x, tid = threadIdx.x;
    const int lane = tid & 31, wid = tid >> 5;
    __shared__ float wacc[6][12];
    __shared__ float racc[12];

    const int hh = tid * 4;
    float a[12];
#pragma unroll
    for (int i = 0; i < 12; i++) a[i] = 0.f;

    float4 v4[3];
    const float4 q4 = *(const float4*)&g_Q[(size_t)b * 768 + hh];
#pragma unroll
    for (int mp = 0; mp < 3; mp++) {
        const float4 k4 = *(const float4*)&g_K[((size_t)b * 3 + mp) * 768 + hh];
        v4[mp]          = *(const float4*)&g_V[((size_t)b * 3 + mp) * 768 + hh];
        const float4 pm = *(const float4*)&p[mp * 768 + hh];
        a[mp] += pm.x * q4.x + pm.y * q4.y + pm.z * q4.z + pm.w * q4.w;

        const float4* hrp = (const float4*)&hmat[((size_t)(mp * 768 + hh)) * 3];
        const float4 f0 = hrp[0], f1 = hrp[1], f2 = hrp[2];
        const float hr[12] = {f0.x, f0.y, f0.z, f0.w, f1.x, f1.y,
                              f1.z, f1.w, f2.x, f2.y, f2.z, f2.w};
        const float t[4] = {q4.x * k4.x, q4.y * k4.y, q4.z * k4.z, q4.w * k4.w};
#pragma unroll
        for (int e = 0; e < 4; e++) {
            a[3] += t[e] * hr[e * 3 + 0];
            a[4] += t[e] * hr[e * 3 + 1];
            a[5] += t[e] * hr[e * 3 + 2];
        }
    }
    const float4 v0 = v4[0], v1 = v4[1], v2 = v4[2];
    a[6]  += v0.x*v0.x + v0.y*v0.y + v0.z*v0.z + v0.w*v0.w;
    a[7]  += v0.x*v1.x + v0.y*v1.y + v0.z*v1.z + v0.w*v1.w;
    a[8]  += v0.x*v2.x + v0.y*v2.y + v0.z*v2.z + v0.w*v2.w;
    a[9]  += v1.x*v1.x + v1.y*v1.y + v1.z*v1.z + v1.w*v1.w;
    a[10] += v1.x*v2.x + v1.y*v2.y + v1.z*v2.z + v1.w*v2.w;
    a[11] += v2.x*v2.x + v2.y*v2.y + v2.z*v2.z + v2.w*v2.w;

#pragma unroll
    for (int i = 0; i < 12; i++) {
        float v = a[i];
#pragma unroll
        for (int off = 16; off; off >>= 1)
            v += __shfl_down_sync(0xffffffffu, v, off);
        if (lane == 0) wacc[wid][i] = v;
    }
    __syncthreads();
    if (tid < 12) {
        float s = 0.f;
#pragma unroll
        for (int w = 0; w < 6; w++) s += wacc[w][tid];
        racc[tid] = s;
    }
    __syncthreads();

    const float ker0 = racc[0] + racc[3];
    const float ker1 = racc[1] + racc[4];
    const float ker2 = racc[2] + racc[5];
    const float c0 = ker0 * racc[6] + ker1 * racc[7]  + ker2 * racc[8];
    const float c1 = ker0 * racc[7] + ker1 * racc[9]  + ker2 * racc[10];
    const float c2 = ker0 * racc[8] + ker1 * racc[10] + ker2 * racc[11];
    const float4 g0 = *(const float4*)&g[hh];
    const float4 g1 = *(const float4*)&g[768 + hh];
    const float4 g2 = *(const float4*)&g[1536 + hh];
    float4 o;
    o.x = ker0*v4[0].x + ker1*v4[1].x + ker2*v4[2].x + c0*g0.x + c1*g1.x + c2*g2.x;
    o.y = ker0*v4[0].y + ker1*v4[1].y + ker2*v4[2].y + c0*g0.y + c1*g1.y + c2*g2.y;
    o.z = ker0*v4[0].z + ker1*v4[1].z + ker2*v4[2].z + c0*g0.z + c1*g1.z + c2*g2.z;
    o.w = ker0*v4[0].w + ker1*v4[1].w + ker2*v4[2].w + c0*g0.w + c1*g1.w + c2*g2.w;
    *(float4*)&out[(size_t)b * 768 + hh] = o;
}

// ---------------- launch -----------------------------------------------------
extern "C" void kernel_launch(void* const* d_in, const int* in_sizes, int n_in,
                              void* d_out, int out_size) {
    const float* target = (const float*)d_in[0];
    const float* cont   = (const float*)d_in[1];
    const float* Wq     = (const float*)d_in[2];
    const float* bq     = (const float*)d_in[3];
    const float* Wk     = (const float*)d_in[4];
    const float* bk     = (const float*)d_in[5];
    const float* Wv     = (const float*)d_in[6];
    const float* bv     = (const float*)d_in[7];
    const float* p      = (const float*)d_in[8];
    const float* hmat   = (const float*)d_in[9];
    const float* g      = (const float*)d_in[10];
    float* out = (float*)d_out;

    qkv_gemm_f16<<<112, 256>>>(target, cont, Wq, Wk, Wv, bq, bk, bv);
    batch_epilogue<<<512, 192>>>(p, hmat, g, out);
}

// round 11
// speedup vs baseline: 2.4848x; 1.1801x over previous
#include <cuda_runtime.h>
#include <cuda_fp16.h>
#include <cstdint>
#include <cstddef>

// ---------------- scratch (allocation-free rule: __device__ globals) --------
__device__ float g_Q[512 * 768];
__device__ float g_K[1536 * 768];
__device__ float g_V[1536 * 768];

// ---------------- helpers ---------------------------------------------------
__device__ __forceinline__ void ldmx4(uint32_t* r, uint32_t addr) {
    asm volatile("ldmatrix.sync.aligned.m8n8.x4.shared.b16 {%0,%1,%2,%3}, [%4];"
                 : "=r"(r[0]), "=r"(r[1]), "=r"(r[2]), "=r"(r[3]) : "r"(addr));
}
__device__ __forceinline__ uint32_t smem_u32(const void* p) {
    uint32_t a;
    asm("{ .reg .u64 t; cvta.to.shared.u64 t, %1; cvt.u32.u64 %0, t; }" : "=r"(a) : "l"(p));
    return a;
}
__device__ __forceinline__ void mma_f16(float* c, const uint32_t* a,
                                        uint32_t b0, uint32_t b1) {
    asm volatile(
        "mma.sync.aligned.m16n8k16.row.col.f32.f16.f16.f32 "
        "{%0,%1,%2,%3}, {%4,%5,%6,%7}, {%8,%9}, {%0,%1,%2,%3};"
        : "+f"(c[0]), "+f"(c[1]), "+f"(c[2]), "+f"(c[3])
        : "r"(a[0]), "r"(a[1]), "r"(a[2]), "r"(a[3]), "r"(b0), "r"(b1));
}
__device__ __forceinline__ void cvt4h_store(char* base, int off, float4 x) {
    uint2 ph;
    ph.x = (uint32_t)__half_as_ushort(__float2half_rn(x.x)) |
           ((uint32_t)__half_as_ushort(__float2half_rn(x.y)) << 16);
    ph.y = (uint32_t)__half_as_ushort(__float2half_rn(x.z)) |
           ((uint32_t)__half_as_ushort(__float2half_rn(x.w)) << 16);
    *(uint2*)(base + off) = ph;
}

// ---------------- fused QKV GEMM: fp16 mma.sync m16n8k16 (1 term) -----------
// C = A @ W^T + bias, both operands rounded to fp16 (rel err ~4e-4 << 1e-3).
// 112 CTAs (single wave), 256 thr, BM=128 x BN=192, K chunked 16 (48 chunks).
//   [0,16)=Q, [16,64)=K, [64,112)=V.
// smem stage 10KB: A[0,4K) B[4K,10K), 32B swizzled rows; double buffered.
// 8 warps as 2(m) x 4(n): warp tile 64x48 -> 24 mma per warp per chunk.
#define NCH   48
#define STAGE 10240

__global__ __launch_bounds__(256)
void qkv_gemm_f16(const float* __restrict__ target, const float* __restrict__ cont,
                  const float* __restrict__ wq, const float* __restrict__ wk,
                  const float* __restrict__ wv,
                  const float* __restrict__ bq, const float* __restrict__ bk,
                  const float* __restrict__ bv) {
    __shared__ __align__(16) char smem[2 * STAGE];
    const uint32_t sb = smem_u32(smem);

    const int tid = threadIdx.x, lane = tid & 31, wid = tid >> 5;
    const int blk = blockIdx.x;

    int by, bx, plane;
    const float *srcA, *bias;
    float* C;
    if (blk < 16)      { int t = blk;      by = t >> 2; bx = t & 3; srcA = target + (size_t)(by * 128) * 768; plane = 0; bias = bq; C = g_Q; }
    else if (blk < 64) { int t = blk - 16; by = t >> 2; bx = t & 3; srcA = cont   + (size_t)(by * 128) * 768; plane = 1; bias = bk; C = g_K; }
    else               { int t = blk - 64; by = t >> 2; bx = t & 3; srcA = cont   + (size_t)(by * 128) * 768; plane = 2; bias = bv; C = g_V; }
    const float* srcB = (plane == 0 ? wq : (plane == 1 ? wk : wv)) + (size_t)(bx * 192) * 768;

    // --- A decode: 512 fp32-float4 slots per chunk, 2 per thread -------------
    const float* gA[2];
    int dA[2];
#pragma unroll
    for (int i = 0; i < 2; i++) {
        const int id = i * 256 + tid;
        const int row = id >> 2, seg = id & 3;
        gA[i] = srcA + (size_t)row * 768 + seg * 4;
        dA[i] = row * 32 + (((seg >> 1) ^ (row >> 2)) & 1) * 16 + (seg & 1) * 8;
    }
    // --- B decode: 768 fp32-float4 slots per chunk, 3 per thread -------------
    const float* gB[3];
    int dB[3];
#pragma unroll
    for (int i = 0; i < 3; i++) {
        const int id = i * 256 + tid;               // 0..767
        const int row = id >> 2, seg = id & 3;      // row 0..191
        gB[i] = srcB + (size_t)row * 768 + seg * 4;
        dB[i] = 4096 + row * 32 + (((seg >> 1) ^ (row >> 2)) & 1) * 16 + (seg & 1) * 8;
    }

    const int warp_m = (wid >> 2) * 64;
    const int warp_n = (wid & 3) * 48;

    const int a_row = lane & 15;
    const int a_sub = (lane >> 4) & 1;
    const int b_row = ((lane >> 4) & 1) * 8 + (lane & 7);
    const int b_sub = (lane >> 3) & 1;

    float acc[4][6][4];
#pragma unroll
    for (int mf = 0; mf < 4; mf++)
#pragma unroll
        for (int j = 0; j < 6; j++)
#pragma unroll
            for (int i = 0; i < 4; i++) acc[mf][j][i] = 0.f;

    float4 rA[2], rB[3];
    // prologue: chunk 0 -> buf 0
#pragma unroll
    for (int i = 0; i < 2; i++) rA[i] = *(const float4*)(gA[i]);
#pragma unroll
    for (int i = 0; i < 3; i++) rB[i] = *(const float4*)(gB[i]);
#pragma unroll
    for (int i = 0; i < 2; i++) cvt4h_store(smem, dA[i], rA[i]);
#pragma unroll
    for (int i = 0; i < 3; i++) cvt4h_store(smem, dB[i], rB[i]);
    __syncthreads();
    // preload chunk 1
#pragma unroll
    for (int i = 0; i < 2; i++) rA[i] = *(const float4*)(gA[i] + 16);
#pragma unroll
    for (int i = 0; i < 3; i++) rB[i] = *(const float4*)(gB[i] + 16);

    for (int c = 0; c < NCH; c++) {
        const int buf = c & 1;
        const uint32_t st = sb + buf * STAGE;

        uint32_t af[4][4], bf[3][4];
#pragma unroll
        for (int mf = 0; mf < 4; mf++) {
            const int row = warp_m + mf * 16 + a_row;
            ldmx4(af[mf], st + row * 32 + ((a_sub ^ (row >> 2)) & 1) * 16);
        }
#pragma unroll
        for (int ng = 0; ng < 3; ng++) {
            const int row = warp_n + ng * 16 + b_row;
            ldmx4(bf[ng], st + 4096 + row * 32 + ((b_sub ^ (row >> 2)) & 1) * 16);
        }

        const bool more = (c + 1 < NCH);
        if (more) {
            // store chunk c+1 (in regs) into the other buffer
            char* stn = smem + (buf ^ 1) * STAGE;
#pragma unroll
            for (int i = 0; i < 2; i++) cvt4h_store(stn, dA[i], rA[i]);
#pragma unroll
            for (int i = 0; i < 3; i++) cvt4h_store(stn, dB[i], rB[i]);
            // LDG chunk c+2 (clamped); latency hidden under mma below
            const int nc = (c + 2 < NCH) ? (c + 2) : (NCH - 1);
            const size_t off = (size_t)nc * 16;
#pragma unroll
            for (int i = 0; i < 2; i++) rA[i] = *(const float4*)(gA[i] + off);
#pragma unroll
            for (int i = 0; i < 3; i++) rB[i] = *(const float4*)(gB[i] + off);
        }

#pragma unroll
        for (int mf = 0; mf < 4; mf++)
#pragma unroll
            for (int j = 0; j < 6; j++)
                mma_f16(acc[mf][j], af[mf], bf[j >> 1][(j & 1) * 2], bf[j >> 1][(j & 1) * 2 + 1]);

        __syncthreads();
    }

    // epilogue: bias + store fp32
    const int g4 = lane >> 2, t4 = lane & 3;
#pragma unroll
    for (int mf = 0; mf < 4; mf++) {
        const int row = by * 128 + warp_m + mf * 16 + g4;
#pragma unroll
        for (int j = 0; j < 6; j++) {
            const int col = bx * 192 + warp_n + j * 8 + t4 * 2;
            const float2 bb = *(const float2*)&bias[col];
            float2 o0, o1;
            o0.x = acc[mf][j][0] + bb.x; o0.y = acc[mf][j][1] + bb.y;
            o1.x = acc[mf][j][2] + bb.x; o1.y = acc[mf][j][3] + bb.y;
            *(float2*)&C[(size_t)row * 768 + col]       = o0;
            *(float2*)&C[(size_t)(row + 8) * 768 + col] = o1;
        }
    }
}

// ---------------- per-batch epilogue: 2 batches per block (ILP + hmat reuse)
__global__ __launch_bounds__(192)
void batch_epilogue(const float* __restrict__ p, const float* __restrict__ hmat,
                    const float* __restrict__ g, float* __restrict__ out) {
    const int b0 = blockIdx.x * 2, tid = threadIdx.x;
    const int lane = tid & 31, wid = tid >> 5;
    __shared__ float wacc[6][24];
    __shared__ float racc[24];

    const int hh = tid * 4;
    float a[2][12];
#pragma unroll
    for (int bb = 0; bb < 2; bb++)
#pragma unroll
        for (int i = 0; i < 12; i++) a[bb][i] = 0.f;

    float4 v4[2][3], q4[2];
    q4[0] = *(const float4*)&g_Q[(size_t)b0 * 768 + hh];
    q4[1] = *(const float4*)&g_Q[(size_t)(b0 + 1) * 768 + hh];
#pragma unroll
    for (int mp = 0; mp < 3; mp++) {
        const float4 pm = *(const float4*)&p[mp * 768 + hh];
        const float4* hrp = (const float4*)&hmat[((size_t)(mp * 768 + hh)) * 3];
        const float4 f0 = hrp[0], f1 = hrp[1], f2 = hrp[2];
        const float hr[12] = {f0.x, f0.y, f0.z, f0.w, f1.x, f1.y,
                              f1.z, f1.w, f2.x, f2.y, f2.z, f2.w};
#pragma unroll
        for (int bb = 0; bb < 2; bb++) {
            const int b = b0 + bb;
            const float4 k4 = *(const float4*)&g_K[((size_t)b * 3 + mp) * 768 + hh];
            v4[bb][mp]      = *(const float4*)&g_V[((size_t)b * 3 + mp) * 768 + hh];
            const float4 q = q4[bb];
            a[bb][mp] += pm.x * q.x + pm.y * q.y + pm.z * q.z + pm.w * q.w;
            const float t[4] = {q.x * k4.x, q.y * k4.y, q.z * k4.z, q.w * k4.w};
#pragma unroll
            for (int e = 0; e < 4; e++) {
                a[bb][3] += t[e] * hr[e * 3 + 0];
                a[bb][4] += t[e] * hr[e * 3 + 1];
                a[bb][5] += t[e] * hr[e * 3 + 2];
            }
        }
    }
#pragma unroll
    for (int bb = 0; bb < 2; bb++) {
        const float4 v0 = v4[bb][0], v1 = v4[bb][1], v2 = v4[bb][2];
        a[bb][6]  += v0.x*v0.x + v0.y*v0.y + v0.z*v0.z + v0.w*v0.w;
        a[bb][7]  += v0.x*v1.x + v0.y*v1.y + v0.z*v1.z + v0.w*v1.w;
        a[bb][8]  += v0.x*v2.x + v0.y*v2.y + v0.z*v2.z + v0.w*v2.w;
        a[bb][9]  += v1.x*v1.x + v1.y*v1.y + v1.z*v1.z + v1.w*v1.w;
        a[bb][10] += v1.x*v2.x + v1.y*v2.y + v1.z*v2.z + v1.w*v2.w;
        a[bb][11] += v2.x*v2.x + v2.y*v2.y + v2.z*v2.z + v2.w*v2.w;
    }

#pragma unroll
    for (int bb = 0; bb < 2; bb++)
#pragma unroll
        for (int i = 0; i < 12; i++) {
            float v = a[bb][i];
#pragma unroll
            for (int off = 16; off; off >>= 1)
                v += __shfl_down_sync(0xffffffffu, v, off);
            if (lane == 0) wacc[wid][bb * 12 + i] = v;
        }
    __syncthreads();
    if (tid < 24) {
        float s = 0.f;
#pragma unroll
        for (int w = 0; w < 6; w++) s += wacc[w][tid];
        racc[tid] = s;
    }
    __syncthreads();

    const float4 g0 = *(const float4*)&g[hh];
    const float4 g1 = *(const float4*)&g[768 + hh];
    const float4 g2 = *(const float4*)&g[1536 + hh];
#pragma unroll
    for (int bb = 0; bb < 2; bb++) {
        const float* rc = &racc[bb * 12];
        const float ker0 = rc[0] + rc[3];
        const float ker1 = rc[1] + rc[4];
        const float ker2 = rc[2] + rc[5];
        const float c0 = ker0 * rc[6] + ker1 * rc[7]  + ker2 * rc[8];
        const float c1 = ker0 * rc[7] + ker1 * rc[9]  + ker2 * rc[10];
        const float c2 = ker0 * rc[8] + ker1 * rc[10] + ker2 * rc[11];
        const float4 v0 = v4[bb][0], v1 = v4[bb][1], v2 = v4[bb][2];
        float4 o;
        o.x = ker0*v0.x + ker1*v1.x + ker2*v2.x + c0*g0.x + c1*g1.x + c2*g2.x;
        o.y = ker0*v0.y + ker1*v1.y + ker2*v2.y + c0*g0.y + c1*g1.y + c2*g2.y;
        o.z = ker0*v0.z + ker1*v1.z + ker2*v2.z + c0*g0.z + c1*g1.z + c2*g2.z;
        o.w = ker0*v0.w + ker1*v1.w + ker2*v2.w + c0*g0.w + c1*g1.w + c2*g2.w;
        *(float4*)&out[(size_t)(b0 + bb) * 768 + hh] = o;
    }
}

// ---------------- launch -----------------------------------------------------
extern "C" void kernel_launch(void* const* d_in, const int* in_sizes, int n_in,
                              void* d_out, int out_size) {
    const float* target = (const float*)d_in[0];
    const float* cont   = (const float*)d_in[1];
    const float* Wq     = (const float*)d_in[2];
    const float* bq     = (const float*)d_in[3];
    const float* Wk     = (const float*)d_in[4];
    const float* bk     = (const float*)d_in[5];
    const float* Wv     = (const float*)d_in[6];
    const float* bv     = (const float*)d_in[7];
    const float* p      = (const float*)d_in[8];
    const float* hmat   = (const float*)d_in[9];
    const float* g      = (const float*)d_in[10];
    float* out = (float*)d_out;

    qkv_gemm_f16<<<112, 256>>>(target, cont, Wq, Wk, Wv, bq, bk, bv);
    batch_epilogue<<<256, 192>>>(p, hmat, g, out);
}